// round 3
// baseline (speedup 1.0000x reference)
#include <cuda_runtime.h>

#define K_TOTAL 100000
#define KC      256
#define NB      ((K_TOTAL + KC - 1) / KC)   // 391
#define SEQ     64
#define G4      200                          // 4*H
#define HID     50
#define SG      (SEQ * G4)                   // 12800

#define RGROUPS 16
#define RSPAN   25                            // 16*25 = 400 >= 391

// Scratch (device globals: allocation-free per harness rules)
__device__ float g_partial[NB * SG];          // ~20 MB
__device__ float g_p2[RGROUPS * SG];          // 800 KB
__device__ float g_gates[SG];

typedef unsigned long long ull;

__device__ __forceinline__ ull pack2(float a, float b) {
    ull r; asm("mov.b64 %0, {%1, %2};" : "=l"(r) : "f"(a), "f"(b)); return r;
}
__device__ __forceinline__ ull packdup(float a) {
    ull r; asm("mov.b64 %0, {%1, %1};" : "=l"(r) : "f"(a)); return r;
}
__device__ __forceinline__ void fma2(ull& d, ull a, ull b) {
    asm("fma.rn.f32x2 %0, %1, %2, %0;" : "+l"(d) : "l"(a), "l"(b));
}
__device__ __forceinline__ ull add2(ull a, ull b) {
    ull r; asm("add.rn.f32x2 %0, %1, %2;" : "=l"(r) : "l"(a), "l"(b)); return r;
}
__device__ __forceinline__ float lo32(ull v) { return __uint_as_float((unsigned)(v & 0xffffffffu)); }
__device__ __forceinline__ float hi32(ull v) { return __uint_as_float((unsigned)(v >> 32)); }

// ---------------------------------------------------------------------------
// Phase A: split-K GEMM partials.
// 400 threads: thread t -> gq = t%50 (gates 4gq..4gq+3), sh = t/50 (s = 8sh..8sh+7)
// ---------------------------------------------------------------------------
__global__ void __launch_bounds__(400, 2) gemm_partial(
    const float* __restrict__ x, const float* __restrict__ Wi)
{
    extern __shared__ float xs[];   // KC*64 floats, [j][s] transposed, 16B-swizzled
    const int t  = threadIdx.x;
    const int k0 = blockIdx.x * KC;

    // ---- load x chunk: 4s x 4j register transpose, swizzled STS.128 ----
    for (int tile = t; tile < (KC / 4) * 16; tile += 400) {
        const int tj = tile & (KC / 4 - 1);   // j-group 0..63
        const int ts = tile >> 6;             // s-group 0..15
        const int jg = tj * 4;
        float4 rv[4];
        #pragma unroll
        for (int u = 0; u < 4; u++) {
            const int s  = ts * 4 + u;
            const int gj = k0 + jg;
            const float* px = x + (size_t)s * K_TOTAL + gj;
            if (gj + 3 < K_TOTAL) {
                rv[u] = *(const float4*)px;
            } else {
                float a = (gj + 0 < K_TOTAL) ? px[0] : 0.f;
                float b = (gj + 1 < K_TOTAL) ? px[1] : 0.f;
                float c = (gj + 2 < K_TOTAL) ? px[2] : 0.f;
                float d = (gj + 3 < K_TOTAL) ? px[3] : 0.f;
                rv[u] = make_float4(a, b, c, d);
            }
        }
        const float* rf = reinterpret_cast<const float*>(rv);
        #pragma unroll
        for (int v = 0; v < 4; v++) {
            const int j    = jg + v;
            const int idx4 = j * 16 + (ts ^ (j & 15));
            float4 c4 = make_float4(rf[0 * 4 + v], rf[1 * 4 + v], rf[2 * 4 + v], rf[3 * 4 + v]);
            *(float4*)(xs + idx4 * 4) = c4;
        }
    }
    __syncthreads();

    const int gq = t % 50;
    const int sh = t / 50;            // 0..7

    ull acc[4][4];
    #pragma unroll
    for (int a = 0; a < 4; a++)
        #pragma unroll
        for (int b = 0; b < 4; b++) acc[a][b] = 0ull;

    const float* wrow = Wi + (size_t)k0 * G4 + gq * 4;
    const int rem  = K_TOTAL - k0;
    const int jend = rem < KC ? rem : KC;    // always a multiple of 4 here

    float4 wc[4], wn[4];
    #pragma unroll
    for (int u = 0; u < 4; u++)
        wc[u] = *(const float4*)(wrow + (size_t)u * G4);

    const int g0 = (2 * sh) & 15;
    const int g1 = (2 * sh + 1) & 15;

    for (int jb = 0; jb < jend; jb += 4) {
        #pragma unroll
        for (int u = 0; u < 4; u++) {
            const int jn = jb + 4 + u;
            wn[u] = (jn < jend) ? *(const float4*)(wrow + (size_t)jn * G4)
                                : make_float4(0.f, 0.f, 0.f, 0.f);
        }
        #pragma unroll
        for (int u = 0; u < 4; u++) {
            const int j  = jb + u;
            const int jm = j & 15;
            const int jbase = j * 16;
            const ull wp0 = packdup(wc[u].x), wp1 = packdup(wc[u].y);
            const ull wp2 = packdup(wc[u].z), wp3 = packdup(wc[u].w);
            const ulonglong2 xa = *(const ulonglong2*)(xs + (jbase + (g0 ^ jm)) * 4);
            const ulonglong2 xb = *(const ulonglong2*)(xs + (jbase + (g1 ^ jm)) * 4);
            fma2(acc[0][0], xa.x, wp0);
            fma2(acc[1][0], xa.x, wp1);
            fma2(acc[2][0], xa.x, wp2);
            fma2(acc[3][0], xa.x, wp3);
            fma2(acc[0][1], xa.y, wp0);
            fma2(acc[1][1], xa.y, wp1);
            fma2(acc[2][1], xa.y, wp2);
            fma2(acc[3][1], xa.y, wp3);
            fma2(acc[0][2], xb.x, wp0);
            fma2(acc[1][2], xb.x, wp1);
            fma2(acc[2][2], xb.x, wp2);
            fma2(acc[3][2], xb.x, wp3);
            fma2(acc[0][3], xb.y, wp0);
            fma2(acc[1][3], xb.y, wp1);
            fma2(acc[2][3], xb.y, wp2);
            fma2(acc[3][3], xb.y, wp3);
        }
        #pragma unroll
        for (int u = 0; u < 4; u++) wc[u] = wn[u];
    }

    float* pout = g_partial + (size_t)blockIdx.x * SG;
    #pragma unroll
    for (int p = 0; p < 4; p++) {
        const int s0 = sh * 8 + p * 2;
        float4 o0 = make_float4(lo32(acc[0][p]), lo32(acc[1][p]), lo32(acc[2][p]), lo32(acc[3][p]));
        float4 o1 = make_float4(hi32(acc[0][p]), hi32(acc[1][p]), hi32(acc[2][p]), hi32(acc[3][p]));
        *(float4*)(pout + (size_t)s0 * G4 + gq * 4)       = o0;
        *(float4*)(pout + (size_t)(s0 + 1) * G4 + gq * 4) = o1;
    }
}

// ---------------------------------------------------------------------------
// Phase B: two-stage deterministic split-K reduce + biases
// ---------------------------------------------------------------------------
__global__ void reduce_stage1()
{
    const int idx = blockIdx.x * blockDim.x + threadIdx.x;   // 0..12799
    const int grp = blockIdx.y;                               // 0..15
    if (idx >= SG) return;
    const int b0   = grp * RSPAN;
    const int bend = (b0 + RSPAN < NB) ? (b0 + RSPAN) : NB;
    float s0 = 0.f, s1 = 0.f, s2 = 0.f, s3 = 0.f;
    int b = b0;
    for (; b + 3 < bend; b += 4) {
        s0 += g_partial[(size_t)(b + 0) * SG + idx];
        s1 += g_partial[(size_t)(b + 1) * SG + idx];
        s2 += g_partial[(size_t)(b + 2) * SG + idx];
        s3 += g_partial[(size_t)(b + 3) * SG + idx];
    }
    for (; b < bend; b++) s0 += g_partial[(size_t)b * SG + idx];
    g_p2[(size_t)grp * SG + idx] = (s0 + s1) + (s2 + s3);
}

__global__ void reduce_stage2(const float* __restrict__ bi, const float* __restrict__ bh)
{
    const int idx = blockIdx.x * blockDim.x + threadIdx.x;   // 0..12799
    if (idx >= SG) return;
    float s0 = 0.f, s1 = 0.f, s2 = 0.f, s3 = 0.f;
    #pragma unroll
    for (int b = 0; b < RGROUPS; b += 4) {
        s0 += g_p2[(size_t)(b + 0) * SG + idx];
        s1 += g_p2[(size_t)(b + 1) * SG + idx];
        s2 += g_p2[(size_t)(b + 2) * SG + idx];
        s3 += g_p2[(size_t)(b + 3) * SG + idx];
    }
    const int g = idx % G4;
    g_gates[idx] = (s0 + s1) + (s2 + s3) + bi[g] + bh[g];
}

// ---------------------------------------------------------------------------
// Phase C: sequential LSTM. All gates preloaded to smem; 4-way split chains.
// ---------------------------------------------------------------------------
__device__ __forceinline__ float fast_sigmoid(float v) {
    return 1.f / (1.f + __expf(-v));
}
__device__ __forceinline__ float fast_tanh(float v) {
    return 2.f / (1.f + __expf(-2.f * v)) - 1.f;
}

__global__ void __launch_bounds__(256) lstm_kernel(const float* __restrict__ Wh,
                                                   float* __restrict__ out)
{
    extern __shared__ float sm[];
    float* gates_s = sm;                      // SG floats (51.2 KB)
    float* hbuf    = sm + SG;                 // 64 floats (16B-aligned)
    float* gbuf    = hbuf + 64;               // 200 floats
    const int t = threadIdx.x;

    // Parallel preload of all pre-gates into smem (removes 64 serial DRAM trips)
    {
        const float4* src = (const float4*)g_gates;
        float4* dst = (float4*)gates_s;
        for (int i = t; i < SG / 4; i += 256) dst[i] = src[i];
    }

    ull wp[25];
    if (t < G4) {
        #pragma unroll
        for (int kk = 0; kk < 25; kk++) {
            float w0 = Wh[(2 * kk + 0) * G4 + t];
            float w1 = Wh[(2 * kk + 1) * G4 + t];
            wp[kk] = pack2(w0, w1);
        }
    }
    if (t < 64) hbuf[t] = 0.f;
    float c = 0.f;
    __syncthreads();

    for (int step = 0; step < SEQ; step++) {
        if (t < G4) {
            const float pre = gates_s[step * G4 + t];
            // 4 independent accumulation chains (dep depth ~7 instead of 25)
            ull a0 = 0ull, a1 = 0ull, a2 = 0ull, a3 = 0ull;
            #pragma unroll
            for (int kk = 0; kk < 24; kk += 4) {
                const ull h0 = *(const ull*)(hbuf + 2 * kk);
                const ull h1 = *(const ull*)(hbuf + 2 * kk + 2);
                const ull h2 = *(const ull*)(hbuf + 2 * kk + 4);
                const ull h3 = *(const ull*)(hbuf + 2 * kk + 6);
                fma2(a0, h0, wp[kk]);
                fma2(a1, h1, wp[kk + 1]);
                fma2(a2, h2, wp[kk + 2]);
                fma2(a3, h3, wp[kk + 3]);
            }
            fma2(a0, *(const ull*)(hbuf + 48), wp[24]);
            const ull s = add2(add2(a0, a1), add2(a2, a3));
            gbuf[t] = pre + lo32(s) + hi32(s);
        }
        __syncthreads();
        if (t < HID) {
            const float i = fast_sigmoid(gbuf[t]);
            const float f = fast_sigmoid(gbuf[HID + t]);
            const float g = fast_tanh(gbuf[2 * HID + t]);
            const float o = fast_sigmoid(gbuf[3 * HID + t]);
            c = f * c + i * g;
            hbuf[t] = o * fast_tanh(c);
        }
        __syncthreads();
    }
    if (t < HID) out[t] = hbuf[t];
}

// ---------------------------------------------------------------------------
extern "C" void kernel_launch(void* const* d_in, const int* in_sizes, int n_in,
                              void* d_out, int out_size)
{
    const float* x  = (const float*)d_in[0];
    const float* Wi = (const float*)d_in[1];
    const float* bi = (const float*)d_in[2];
    const float* Wh = (const float*)d_in[3];
    const float* bh = (const float*)d_in[4];
    float* out = (float*)d_out;

    (void)in_sizes; (void)n_in; (void)out_size;

    cudaFuncSetAttribute(gemm_partial, cudaFuncAttributeMaxDynamicSharedMemorySize,
                         KC * 64 * 4);
    const int lstm_smem = (SG + 64 + 200) * 4 + 64;
    cudaFuncSetAttribute(lstm_kernel, cudaFuncAttributeMaxDynamicSharedMemorySize,
                         lstm_smem);

    gemm_partial<<<NB, 400, KC * 64 * 4>>>(x, Wi);
    reduce_stage1<<<dim3(SG / 128, RGROUPS), 128>>>();
    reduce_stage2<<<SG / 128, 128>>>(bi, bh);
    lstm_kernel<<<1, 256, lstm_smem>>>(Wh, out);
}

// round 4
// speedup vs baseline: 1.3170x; 1.3170x over previous
#include <cuda_runtime.h>

#define K_TOTAL 100000
#define KC      256
#define NB      ((K_TOTAL + KC - 1) / KC)   // 391
#define SEQ     64
#define G4      200                          // 4*H
#define HID     50
#define SG      (SEQ * G4)                   // 12800

#define RGROUPS 16
#define RSPAN   25

#define WSTAGE  8                             // j-rows per cp.async stage
#define WBUFS   4                             // ring buffers (prefetch dist 2)

// Scratch (device globals)
__device__ float g_partial[NB * SG];
__device__ float g_p2[RGROUPS * SG];
__device__ float g_gates[SG];

typedef unsigned long long ull;

__device__ __forceinline__ ull pack2(float a, float b) {
    ull r; asm("mov.b64 %0, {%1, %2};" : "=l"(r) : "f"(a), "f"(b)); return r;
}
__device__ __forceinline__ ull packdup(float a) {
    ull r; asm("mov.b64 %0, {%1, %1};" : "=l"(r) : "f"(a)); return r;
}
__device__ __forceinline__ void fma2(ull& d, ull a, ull b) {
    asm("fma.rn.f32x2 %0, %1, %2, %0;" : "+l"(d) : "l"(a), "l"(b));
}
__device__ __forceinline__ ull add2(ull a, ull b) {
    ull r; asm("add.rn.f32x2 %0, %1, %2;" : "=l"(r) : "l"(a), "l"(b)); return r;
}
__device__ __forceinline__ float lo32(ull v) { return __uint_as_float((unsigned)(v & 0xffffffffu)); }
__device__ __forceinline__ float hi32(ull v) { return __uint_as_float((unsigned)(v >> 32)); }

__device__ __forceinline__ void cp_async16(float* smem, const float* gmem) {
    unsigned sa = (unsigned)__cvta_generic_to_shared(smem);
    asm volatile("cp.async.cg.shared.global [%0], [%1], 16;" :: "r"(sa), "l"(gmem));
}
__device__ __forceinline__ void cp_commit() { asm volatile("cp.async.commit_group;"); }
__device__ __forceinline__ void cp_wait2() { asm volatile("cp.async.wait_group 2;"); }
__device__ __forceinline__ void cp_wait1() { asm volatile("cp.async.wait_group 1;"); }
__device__ __forceinline__ void cp_wait0() { asm volatile("cp.async.wait_group 0;"); }

// ---------------------------------------------------------------------------
// Phase A: split-K GEMM partials. 400 threads, 2 CTAs/SM, Wi staged via cp.async.
// thread t -> gq = t%50 (gates 4gq..4gq+3), sh = t/50 (s = 8sh..8sh+7)
// acc[4 g][4 s-pairs] = 16 ull = 32 regs. No register prefetch => no spills.
// ---------------------------------------------------------------------------
__global__ void __launch_bounds__(400, 2) gemm_partial(
    const float* __restrict__ x, const float* __restrict__ Wi)
{
    extern __shared__ float sm[];
    float* xs = sm;                        // KC*64 floats (64 KB), swizzled [j][s]
    float* ws = sm + KC * 64;              // WBUFS * WSTAGE*200 floats (25.6 KB)
    const int t  = threadIdx.x;
    const int k0 = blockIdx.x * KC;

    // ---- stage x chunk: 4s x 4j register transpose, swizzled STS.128 ----
    for (int tile = t; tile < (KC / 4) * 16; tile += 400) {
        const int tj = tile & (KC / 4 - 1);
        const int ts = tile >> 6;
        const int jg = tj * 4;
        float4 rv[4];
        #pragma unroll
        for (int u = 0; u < 4; u++) {
            const int s  = ts * 4 + u;
            const int gj = k0 + jg;
            const float* px = x + (size_t)s * K_TOTAL + gj;
            if (gj + 3 < K_TOTAL) {
                rv[u] = *(const float4*)px;
            } else {
                float a = (gj + 0 < K_TOTAL) ? px[0] : 0.f;
                float b = (gj + 1 < K_TOTAL) ? px[1] : 0.f;
                float c = (gj + 2 < K_TOTAL) ? px[2] : 0.f;
                float d = (gj + 3 < K_TOTAL) ? px[3] : 0.f;
                rv[u] = make_float4(a, b, c, d);
            }
        }
        const float* rf = reinterpret_cast<const float*>(rv);
        #pragma unroll
        for (int v = 0; v < 4; v++) {
            const int j    = jg + v;
            const int idx4 = j * 16 + (ts ^ (j & 15));
            *(float4*)(xs + idx4 * 4) =
                make_float4(rf[0 * 4 + v], rf[1 * 4 + v], rf[2 * 4 + v], rf[3 * 4 + v]);
        }
    }

    const int gq = t % 50;
    const int sh = t / 50;
    const int g0 = (2 * sh) & 15;
    const int g1 = (2 * sh + 1) & 15;

    const int rem    = K_TOTAL - k0;
    const int jend   = rem < KC ? rem : KC;     // 256 or 160, both % 8 == 0
    const int stages = jend / WSTAGE;

    // cp.async staging coords: one 16B op per thread per stage
    const int prow = t / 50;                    // 0..7
    const int pcol = (t % 50) * 4;
    const float* wsrc0 = Wi + ((size_t)k0 + prow) * G4 + pcol;
    float* wdst0 = ws + prow * G4 + pcol;

    // prime pipeline: stages 0 and 1
    cp_async16(wdst0 + (0 % WBUFS) * (WSTAGE * G4), wsrc0 + (size_t)(0 * WSTAGE) * G4);
    cp_commit();
    cp_async16(wdst0 + (1 % WBUFS) * (WSTAGE * G4), wsrc0 + (size_t)(1 * WSTAGE) * G4);
    cp_commit();

    ull acc[4][4];
    #pragma unroll
    for (int a = 0; a < 4; a++)
        #pragma unroll
        for (int b = 0; b < 4; b++) acc[a][b] = 0ull;

    __syncthreads();   // covers xs staging too

    for (int s = 0; s < stages; s++) {
        if (s + 2 < stages) {
            cp_async16(wdst0 + ((s + 2) % WBUFS) * (WSTAGE * G4),
                       wsrc0 + (size_t)((s + 2) * WSTAGE) * G4);
            cp_commit();
            cp_wait2();                       // guarantees stage s landed
        } else if (s + 1 < stages) {
            cp_wait1();
        } else {
            cp_wait0();
        }
        __syncthreads();

        const float* wbuf = ws + (s % WBUFS) * (WSTAGE * G4) + gq * 4;
        const int jb = s * WSTAGE;
        #pragma unroll
        for (int jj = 0; jj < WSTAGE; jj++) {
            const int j  = jb + jj;
            const int jm = j & 15;
            const int jbase = j * 16;
            const float4 w4 = *(const float4*)(wbuf + jj * G4);
            const ull wp0 = packdup(w4.x), wp1 = packdup(w4.y);
            const ull wp2 = packdup(w4.z), wp3 = packdup(w4.w);
            const ulonglong2 xa = *(const ulonglong2*)(xs + (jbase + (g0 ^ jm)) * 4);
            const ulonglong2 xb = *(const ulonglong2*)(xs + (jbase + (g1 ^ jm)) * 4);
            fma2(acc[0][0], xa.x, wp0);
            fma2(acc[1][0], xa.x, wp1);
            fma2(acc[2][0], xa.x, wp2);
            fma2(acc[3][0], xa.x, wp3);
            fma2(acc[0][1], xa.y, wp0);
            fma2(acc[1][1], xa.y, wp1);
            fma2(acc[2][1], xa.y, wp2);
            fma2(acc[3][1], xa.y, wp3);
            fma2(acc[0][2], xb.x, wp0);
            fma2(acc[1][2], xb.x, wp1);
            fma2(acc[2][2], xb.x, wp2);
            fma2(acc[3][2], xb.x, wp3);
            fma2(acc[0][3], xb.y, wp0);
            fma2(acc[1][3], xb.y, wp1);
            fma2(acc[2][3], xb.y, wp2);
            fma2(acc[3][3], xb.y, wp3);
        }
    }

    float* pout = g_partial + (size_t)blockIdx.x * SG;
    #pragma unroll
    for (int p = 0; p < 4; p++) {
        const int s0 = sh * 8 + p * 2;
        float4 o0 = make_float4(lo32(acc[0][p]), lo32(acc[1][p]), lo32(acc[2][p]), lo32(acc[3][p]));
        float4 o1 = make_float4(hi32(acc[0][p]), hi32(acc[1][p]), hi32(acc[2][p]), hi32(acc[3][p]));
        *(float4*)(pout + (size_t)s0 * G4 + gq * 4)       = o0;
        *(float4*)(pout + (size_t)(s0 + 1) * G4 + gq * 4) = o1;
    }
}

// ---------------------------------------------------------------------------
// Phase B: two-stage deterministic split-K reduce + biases
// ---------------------------------------------------------------------------
__global__ void reduce_stage1()
{
    const int idx = blockIdx.x * blockDim.x + threadIdx.x;
    const int grp = blockIdx.y;
    if (idx >= SG) return;
    const int b0   = grp * RSPAN;
    const int bend = (b0 + RSPAN < NB) ? (b0 + RSPAN) : NB;
    float s0 = 0.f, s1 = 0.f, s2 = 0.f, s3 = 0.f;
    int b = b0;
    for (; b + 3 < bend; b += 4) {
        s0 += g_partial[(size_t)(b + 0) * SG + idx];
        s1 += g_partial[(size_t)(b + 1) * SG + idx];
        s2 += g_partial[(size_t)(b + 2) * SG + idx];
        s3 += g_partial[(size_t)(b + 3) * SG + idx];
    }
    for (; b < bend; b++) s0 += g_partial[(size_t)b * SG + idx];
    g_p2[(size_t)grp * SG + idx] = (s0 + s1) + (s2 + s3);
}

__global__ void reduce_stage2(const float* __restrict__ bi, const float* __restrict__ bh)
{
    const int idx = blockIdx.x * blockDim.x + threadIdx.x;
    if (idx >= SG) return;
    float s0 = 0.f, s1 = 0.f, s2 = 0.f, s3 = 0.f;
    #pragma unroll
    for (int b = 0; b < RGROUPS; b += 4) {
        s0 += g_p2[(size_t)(b + 0) * SG + idx];
        s1 += g_p2[(size_t)(b + 1) * SG + idx];
        s2 += g_p2[(size_t)(b + 2) * SG + idx];
        s3 += g_p2[(size_t)(b + 3) * SG + idx];
    }
    const int g = idx % G4;
    g_gates[idx] = (s0 + s1) + (s2 + s3) + bi[g] + bh[g];
}

// ---------------------------------------------------------------------------
// Phase C: sequential LSTM. MUFU tanh.approx activations (single-op).
// ---------------------------------------------------------------------------
__device__ __forceinline__ float tanh_fast(float v) {
    float r; asm("tanh.approx.f32 %0, %1;" : "=f"(r) : "f"(v)); return r;
}
__device__ __forceinline__ float sig_fast(float v) {
    return fmaf(0.5f, tanh_fast(0.5f * v), 0.5f);
}

__global__ void __launch_bounds__(256) lstm_kernel(const float* __restrict__ Wh,
                                                   float* __restrict__ out)
{
    extern __shared__ float sml[];
    float* gates_s = sml;                 // SG floats
    float* hbuf    = sml + SG;            // 64 floats
    float* gbuf    = hbuf + 64;           // 200 floats
    const int t = threadIdx.x;

    {   // parallel preload of pre-gates
        const float4* src = (const float4*)g_gates;
        float4* dst = (float4*)gates_s;
        for (int i = t; i < SG / 4; i += 256) dst[i] = src[i];
    }

    ull wp[25];
    if (t < G4) {
        #pragma unroll
        for (int kk = 0; kk < 25; kk++) {
            float w0 = Wh[(2 * kk + 0) * G4 + t];
            float w1 = Wh[(2 * kk + 1) * G4 + t];
            wp[kk] = pack2(w0, w1);
        }
    }
    if (t < 64) hbuf[t] = 0.f;
    float c = 0.f;
    __syncthreads();

    for (int step = 0; step < SEQ; step++) {
        if (t < G4) {
            const float pre = gates_s[step * G4 + t];
            ull a0 = 0ull, a1 = 0ull, a2 = 0ull, a3 = 0ull;
            #pragma unroll
            for (int kk = 0; kk < 24; kk += 4) {
                const ull h0 = *(const ull*)(hbuf + 2 * kk);
                const ull h1 = *(const ull*)(hbuf + 2 * kk + 2);
                const ull h2 = *(const ull*)(hbuf + 2 * kk + 4);
                const ull h3 = *(const ull*)(hbuf + 2 * kk + 6);
                fma2(a0, h0, wp[kk]);
                fma2(a1, h1, wp[kk + 1]);
                fma2(a2, h2, wp[kk + 2]);
                fma2(a3, h3, wp[kk + 3]);
            }
            fma2(a0, *(const ull*)(hbuf + 48), wp[24]);
            const ull s = add2(add2(a0, a1), add2(a2, a3));
            gbuf[t] = pre + lo32(s) + hi32(s);
        }
        __syncthreads();
        if (t < HID) {
            const float i = sig_fast(gbuf[t]);
            const float f = sig_fast(gbuf[HID + t]);
            const float g = tanh_fast(gbuf[2 * HID + t]);
            const float o = sig_fast(gbuf[3 * HID + t]);
            c = f * c + i * g;
            hbuf[t] = o * tanh_fast(c);
        }
        __syncthreads();
    }
    if (t < HID) out[t] = hbuf[t];
}

// ---------------------------------------------------------------------------
extern "C" void kernel_launch(void* const* d_in, const int* in_sizes, int n_in,
                              void* d_out, int out_size)
{
    const float* x  = (const float*)d_in[0];
    const float* Wi = (const float*)d_in[1];
    const float* bi = (const float*)d_in[2];
    const float* Wh = (const float*)d_in[3];
    const float* bh = (const float*)d_in[4];
    float* out = (float*)d_out;

    (void)in_sizes; (void)n_in; (void)out_size;

    const int gemm_smem = (KC * 64 + WBUFS * WSTAGE * G4) * 4;   // 89.6 KB
    cudaFuncSetAttribute(gemm_partial, cudaFuncAttributeMaxDynamicSharedMemorySize,
                         gemm_smem);
    const int lstm_smem = (SG + 64 + 200) * 4 + 64;
    cudaFuncSetAttribute(lstm_kernel, cudaFuncAttributeMaxDynamicSharedMemorySize,
                         lstm_smem);

    gemm_partial<<<NB, 400, gemm_smem>>>(x, Wi);
    reduce_stage1<<<dim3(SG / 128, RGROUPS), 128>>>();
    reduce_stage2<<<SG / 128, 128>>>(bi, bh);
    lstm_kernel<<<1, 256, lstm_smem>>>(Wh, out);
}